// round 15
// baseline (speedup 1.0000x reference)
#include <cuda_runtime.h>
#include <cstdint>

// ---------------- problem constants ----------------
#define Nn   100000
#define Ee   600000
#define Gg   64
#define FIN  32
#define Wd   128
#define EPSv 1e-5f

// ---------------- device scratch (static, no allocs) ----------------
__device__ float g_h[(size_t)Nn * Wd];     // conv output; also [N,32] xa for conv1
__device__ float g_a[(size_t)Nn * Wd];     // activations / self-base (in-place gather)
__device__ float g_dinv[Nn];
__device__ int   g_deg[Nn];
__device__ float g_stats[2 * Wd];
__device__ float g_pool[Gg * Wd];
// CSR (edges grouped by dst)
__device__ int   g_rowptr[Nn + 1];
__device__ int   g_cursor[Nn];
__device__ int   g_esrc[Ee];
__device__ int   g_blk[512];

#define SCAN_BLOCKS 391

// ---------------- zero / degree ----------------
__global__ void k_zero_misc() {
    int i = blockIdx.x * blockDim.x + threadIdx.x;
    if (i < Nn) { g_deg[i] = 0; g_cursor[i] = 0; }
    if (i < 2 * Wd) g_stats[i] = 0.f;
    if (i < Gg * Wd) g_pool[i] = 0.f;
}

__global__ void k_deg(const int* __restrict__ dst) {
    int e = blockIdx.x * blockDim.x + threadIdx.x;
    if (e < Ee) atomicAdd(&g_deg[dst[e]], 1);
}

// ---------------- CSR build (scan1 also computes dinv) ----------------
__global__ void k_scan1() {
    __shared__ int sh[256];
    int i = blockIdx.x * 256 + threadIdx.x;
    int d = (i < Nn) ? g_deg[i] : 0;
    if (i < Nn) g_dinv[i] = rsqrtf((float)d + 1.0f);
    sh[threadIdx.x] = d;
    __syncthreads();
    for (int s = 128; s > 0; s >>= 1) {
        if (threadIdx.x < s) sh[threadIdx.x] += sh[threadIdx.x + s];
        __syncthreads();
    }
    if (threadIdx.x == 0) g_blk[blockIdx.x] = sh[0];
}

__global__ void k_scan2() {
    __shared__ int sh[512];
    int t = threadIdx.x;
    sh[t] = (t < SCAN_BLOCKS) ? g_blk[t] : 0;
    __syncthreads();
    int val = sh[t];
    for (int off = 1; off < 512; off <<= 1) {
        int v = (t >= off) ? sh[t - off] : 0;
        __syncthreads();
        sh[t] += v;
        __syncthreads();
    }
    if (t < SCAN_BLOCKS) g_blk[t] = sh[t] - val;
    if (t == 0) g_rowptr[Nn] = Ee;
}

__global__ void k_scan3() {
    __shared__ int sh[256];
    int i = blockIdx.x * 256 + threadIdx.x;
    int t = threadIdx.x;
    int val = (i < Nn) ? g_deg[i] : 0;
    sh[t] = val;
    __syncthreads();
    for (int off = 1; off < 256; off <<= 1) {
        int v = (t >= off) ? sh[t - off] : 0;
        __syncthreads();
        sh[t] += v;
        __syncthreads();
    }
    if (i < Nn) g_rowptr[i] = g_blk[blockIdx.x] + sh[t] - val;
}

__global__ void k_fill(const int* __restrict__ src, const int* __restrict__ dst) {
    int e = blockIdx.x * blockDim.x + threadIdx.x;
    if (e >= Ee) return;
    int d = dst[e];
    int pos = g_rowptr[d] + atomicAdd(&g_cursor[d], 1);
    g_esrc[pos] = src[e];
}

// ---------------- gather32: xa[n] = dinv^2*x[n] + sum_e dinv_s*dinv_n*x[s] ----------------
// one warp per node, 1 feature (of 32) per lane; writes g_h used as [N,32].
__global__ void k_gather32(const float* __restrict__ x) {
    int n = blockIdx.x * 8 + (threadIdx.x >> 5);
    if (n >= Nn) return;
    int lane = threadIdx.x & 31;
    int beg = g_rowptr[n], end = g_rowptr[n + 1];
    float dn = g_dinv[n];
    float acc = x[(size_t)n * FIN + lane] * dn * dn;
    int e = beg;
    for (; e + 4 <= end; e += 4) {
        int s0 = g_esrc[e], s1 = g_esrc[e + 1], s2 = g_esrc[e + 2], s3 = g_esrc[e + 3];
        float w0 = g_dinv[s0] * dn, w1 = g_dinv[s1] * dn;
        float w2 = g_dinv[s2] * dn, w3 = g_dinv[s3] * dn;
        float v0 = x[(size_t)s0 * FIN + lane];
        float v1 = x[(size_t)s1 * FIN + lane];
        float v2 = x[(size_t)s2 * FIN + lane];
        float v3 = x[(size_t)s3 * FIN + lane];
        acc = fmaf(v0, w0, acc);
        acc = fmaf(v1, w1, acc);
        acc = fmaf(v2, w2, acc);
        acc = fmaf(v3, w3, acc);
    }
    for (; e < end; e++) {
        int s = g_esrc[e];
        acc = fmaf(x[(size_t)s * FIN + lane], g_dinv[s] * dn, acc);
    }
    g_h[(size_t)n * FIN + lane] = acc;
}

// ---------------- CSR gather 128-wide, 2 warps per node (float2 lanes) ----------------
// in-place on g_a (base written by GEMM SELF epilogue); 4x unrolled edge loop.
__global__ void k_gather() {
    int n = blockIdx.x * 4 + (threadIdx.x >> 6);          // 4 nodes per 256-thr block
    if (n >= Nn) return;
    int half = (threadIdx.x >> 5) & 1;                    // which 64-col half
    int lane = threadIdx.x & 31;
    int off  = half * 64 + lane * 2;                      // float2 column offset
    int beg = g_rowptr[n], end = g_rowptr[n + 1];
    float dn = g_dinv[n];
    float2 acc = *(const float2*)&g_a[(size_t)n * Wd + off];
    int e = beg;
    for (; e + 4 <= end; e += 4) {
        int s0 = g_esrc[e], s1 = g_esrc[e + 1], s2 = g_esrc[e + 2], s3 = g_esrc[e + 3];
        float w0 = g_dinv[s0] * dn, w1 = g_dinv[s1] * dn;
        float w2 = g_dinv[s2] * dn, w3 = g_dinv[s3] * dn;
        float2 v0 = *(const float2*)&g_h[(size_t)s0 * Wd + off];
        float2 v1 = *(const float2*)&g_h[(size_t)s1 * Wd + off];
        float2 v2 = *(const float2*)&g_h[(size_t)s2 * Wd + off];
        float2 v3 = *(const float2*)&g_h[(size_t)s3 * Wd + off];
        acc.x = fmaf(v0.x, w0, acc.x); acc.y = fmaf(v0.y, w0, acc.y);
        acc.x = fmaf(v1.x, w1, acc.x); acc.y = fmaf(v1.y, w1, acc.y);
        acc.x = fmaf(v2.x, w2, acc.x); acc.y = fmaf(v2.y, w2, acc.y);
        acc.x = fmaf(v3.x, w3, acc.x); acc.y = fmaf(v3.y, w3, acc.y);
    }
    for (; e < end; e++) {
        int s = g_esrc[e];
        float w = g_dinv[s] * dn;
        float2 v = *(const float2*)&g_h[(size_t)s * Wd + off];
        acc.x = fmaf(v.x, w, acc.x); acc.y = fmaf(v.y, w, acc.y);
    }
    *(float2*)&g_a[(size_t)n * Wd + off] = acc;
}

// ---------------- fused fp32 SGEMM v2 (proven best) ----------------
// 128x128 tile, 256 threads, 8x8 microtile, packed fma.rn.f32x2,
// double-buffered smem, reg prefetch, 2 CTAs/SM.
enum { LOAD_NONE = 0, LOAD_RELU = 1, LOAD_BN = 2 };

template <int LOADM, bool BIAS, bool RELU, bool SELF, bool STATS>
__global__ __launch_bounds__(256, 2) void k_gemm(const float* __restrict__ A,
                                                 const float* __restrict__ Bm,
                                                 const float* __restrict__ bias,
                                                 float* __restrict__ C, int K) {
    __shared__ float As[2][16][132];
    __shared__ float Bs[2][16][128];
    __shared__ float s_st[2][128];

    int tid = threadIdx.x;
    int rb  = blockIdx.x * 128;
    int tx  = tid & 15;
    int ty  = tid >> 4;
    int lr  = tid >> 2;
    int kq  = (tid & 3) * 4;
    int bk  = tid >> 4;
    int bc  = (tid & 15) * 8;

    float4 pa[2], pb[2];

    auto ldTile = [&](int kc) {
#pragma unroll
        for (int h = 0; h < 2; h++) {
            int r = rb + lr + h * 64;
            float4 v = make_float4(0.f, 0.f, 0.f, 0.f);
            if (r < Nn) v = *(const float4*)&A[(size_t)r * K + kc * 16 + kq];
            pa[h] = v;
        }
        const float* bp = &Bm[(size_t)(kc * 16 + bk) * Wd + bc];
        pb[0] = *(const float4*)bp;
        pb[1] = *(const float4*)(bp + 4);
    };

    auto stTile = [&](int buf, int kc) {
#pragma unroll
        for (int h = 0; h < 2; h++) {
            float4 v = pa[h];
            if (LOADM == LOAD_RELU) {
                v.x = fmaxf(v.x, 0.f); v.y = fmaxf(v.y, 0.f);
                v.z = fmaxf(v.z, 0.f); v.w = fmaxf(v.w, 0.f);
            } else if (LOADM == LOAD_BN) {
                int c0 = kc * 16 + kq;
                v.x = fmaxf(fmaf(v.x, g_stats[c0 + 0], g_stats[Wd + c0 + 0]), 0.f);
                v.y = fmaxf(fmaf(v.y, g_stats[c0 + 1], g_stats[Wd + c0 + 1]), 0.f);
                v.z = fmaxf(fmaf(v.z, g_stats[c0 + 2], g_stats[Wd + c0 + 2]), 0.f);
                v.w = fmaxf(fmaf(v.w, g_stats[c0 + 3], g_stats[Wd + c0 + 3]), 0.f);
            }
            As[buf][kq + 0][lr + h * 64] = v.x;
            As[buf][kq + 1][lr + h * 64] = v.y;
            As[buf][kq + 2][lr + h * 64] = v.z;
            As[buf][kq + 3][lr + h * 64] = v.w;
        }
        *(float4*)&Bs[buf][bk][bc]     = pb[0];
        *(float4*)&Bs[buf][bk][bc + 4] = pb[1];
    };

    unsigned long long acc[8][4];
#pragma unroll
    for (int i = 0; i < 8; i++)
#pragma unroll
        for (int j = 0; j < 4; j++) acc[i][j] = 0ull;

    int nk = K >> 4;
    ldTile(0);
    stTile(0, 0);
    __syncthreads();

    for (int kc = 0; kc < nk; kc++) {
        if (kc + 1 < nk) ldTile(kc + 1);
        int buf = kc & 1;
#pragma unroll
        for (int k = 0; k < 16; k++) {
            float4 a0 = *(const float4*)&As[buf][k][ty * 8];
            float4 a1 = *(const float4*)&As[buf][k][ty * 8 + 4];
            ulonglong2 b0 = *(const ulonglong2*)&Bs[buf][k][tx * 8];
            ulonglong2 b1 = *(const ulonglong2*)&Bs[buf][k][tx * 8 + 4];
            unsigned long long bb[4] = {b0.x, b0.y, b1.x, b1.y};
            float av[8] = {a0.x, a0.y, a0.z, a0.w, a1.x, a1.y, a1.z, a1.w};
#pragma unroll
            for (int i = 0; i < 8; i++) {
                unsigned long long ad;
                unsigned int ai = __float_as_uint(av[i]);
                asm("mov.b64 %0, {%1, %1};" : "=l"(ad) : "r"(ai));
#pragma unroll
                for (int j = 0; j < 4; j++)
                    asm("fma.rn.f32x2 %0, %1, %2, %0;"
                        : "+l"(acc[i][j]) : "l"(ad), "l"(bb[j]));
            }
        }
        if (kc + 1 < nk) {
            stTile((kc + 1) & 1, kc + 1);
            __syncthreads();
        }
    }

    // ---------------- epilogue ----------------
    if (STATS) {
        s_st[tid >> 7][tid & 127] = 0.f;
        __syncthreads();
    }

    float cs[8], cq[8];
    if (STATS) {
#pragma unroll
        for (int j = 0; j < 8; j++) { cs[j] = 0.f; cq[j] = 0.f; }
    }

#pragma unroll
    for (int i = 0; i < 8; i++) {
        int r = rb + ty * 8 + i;
        if (r < Nn) {
            float out[8];
#pragma unroll
            for (int j = 0; j < 4; j++) {
                union { unsigned long long u; float2 f; } t;
                t.u = acc[i][j];
                out[2 * j]     = t.f.x;
                out[2 * j + 1] = t.f.y;
            }
            float os[8];
#pragma unroll
            for (int j = 0; j < 8; j++) {
                float v = out[j];
                if (BIAS) v += bias[tx * 8 + j];
                if (RELU) v = fmaxf(v, 0.f);
                os[j] = v;
                if (STATS) { cs[j] += v; cq[j] += v * v; }
            }
            float* cp = &C[(size_t)r * Wd + tx * 8];
            *(float4*)(cp)     = make_float4(os[0], os[1], os[2], os[3]);
            *(float4*)(cp + 4) = make_float4(os[4], os[5], os[6], os[7]);
            if (SELF) {
                float dv = g_dinv[r];
                float ds = dv * dv;
                float* ap = &g_a[(size_t)r * Wd + tx * 8];
                float4 s0, s1;
                s0.x = fmaf(out[0], ds, bias[tx * 8 + 0]);
                s0.y = fmaf(out[1], ds, bias[tx * 8 + 1]);
                s0.z = fmaf(out[2], ds, bias[tx * 8 + 2]);
                s0.w = fmaf(out[3], ds, bias[tx * 8 + 3]);
                s1.x = fmaf(out[4], ds, bias[tx * 8 + 4]);
                s1.y = fmaf(out[5], ds, bias[tx * 8 + 5]);
                s1.z = fmaf(out[6], ds, bias[tx * 8 + 6]);
                s1.w = fmaf(out[7], ds, bias[tx * 8 + 7]);
                *(float4*)(ap)     = s0;
                *(float4*)(ap + 4) = s1;
            }
        }
    }

    if (STATS) {
#pragma unroll
        for (int j = 0; j < 8; j++) {
            atomicAdd(&s_st[0][tx * 8 + j], cs[j]);
            atomicAdd(&s_st[1][tx * 8 + j], cq[j]);
        }
        __syncthreads();
        if (tid < 128) {
            atomicAdd(&g_stats[tid],      s_st[0][tid]);
            atomicAdd(&g_stats[Wd + tid], s_st[1][tid]);
        }
    }
}

// ---------------- BN finalize ----------------
__global__ void k_bnfin(const float* __restrict__ gamma, const float* __restrict__ beta) {
    int c = threadIdx.x;  // 128
    float mu  = g_stats[c] * (1.f / Nn);
    float var = g_stats[Wd + c] * (1.f / Nn) - mu * mu;
    float rs  = rsqrtf(var + EPSv);
    float sc  = gamma[c] * rs;
    g_stats[c]      = sc;
    g_stats[Wd + c] = beta[c] - mu * sc;
}

// ---------------- per-graph max pool (batch is sorted) ----------------
#define POOL_ROWS 500
__global__ void k_segmax(const int* __restrict__ batch) {
    int c  = threadIdx.x;
    int r0 = blockIdx.x * POOL_ROWS;
    int r1 = r0 + POOL_ROWS;
    int cur = batch[r0];
    float m = g_a[(size_t)r0 * Wd + c];
    for (int r = r0 + 1; r < r1; r++) {
        int gID = batch[r];
        float v = g_a[(size_t)r * Wd + c];
        if (gID != cur) {
            atomicMax((int*)&g_pool[cur * Wd + c], __float_as_int(m));
            cur = gID;
            m = v;
        } else {
            m = fmaxf(m, v);
        }
    }
    atomicMax((int*)&g_pool[cur * Wd + c], __float_as_int(m));
}

// ---------------- head MLP ----------------
__global__ void k_final(const float* __restrict__ W5, const float* __restrict__ b5,
                        const float* __restrict__ g2, const float* __restrict__ be2,
                        const float* __restrict__ W6, const float* __restrict__ b6,
                        float* __restrict__ out) {
    __shared__ float S[64][65];
    __shared__ float sc[64], tc[64];
    int tid = threadIdx.x;
    for (int idx = tid; idx < 64 * 64; idx += 256) {
        int r = idx >> 6, c = idx & 63;
        float acc = b5[c];
        for (int k = 0; k < 128; k++) acc = fmaf(g_pool[r * 128 + k], W5[k * 64 + c], acc);
        S[r][c] = acc;
    }
    __syncthreads();
    if (tid < 64) {
        int c = tid;
        float s = 0.f, q = 0.f;
        for (int r = 0; r < 64; r++) { float v = S[r][c]; s += v; q += v * v; }
        float mu  = s * (1.f / 64);
        float var = q * (1.f / 64) - mu * mu;
        float rs  = rsqrtf(var + EPSv);
        float s_  = g2[c] * rs;
        sc[c] = s_;
        tc[c] = be2[c] - mu * s_;
    }
    __syncthreads();
    if (tid < 64) {
        int r = tid;
        float o = b6[0];
        for (int c = 0; c < 64; c++) {
            float v = fmaxf(fmaf(S[r][c], sc[c], tc[c]), 0.f);
            o = fmaf(v, W6[c], o);
        }
        out[r] = o;
    }
}

// ---------------- launch ----------------
extern "C" void kernel_launch(void* const* d_in, const int* in_sizes, int n_in,
                              void* d_out, int out_size) {
    const float* x    = (const float*)d_in[0];
    const int*   ei   = (const int*)d_in[1];
    const int*   src  = ei;
    const int*   dst  = ei + Ee;
    const int*   batch= (const int*)d_in[2];
    const float* W1 = (const float*)d_in[3];
    const float* b1 = (const float*)d_in[4];
    const float* W2 = (const float*)d_in[5];
    const float* b2 = (const float*)d_in[6];
    const float* W3 = (const float*)d_in[7];
    const float* b3 = (const float*)d_in[8];
    const float* g1 = (const float*)d_in[9];
    const float* be1= (const float*)d_in[10];
    const float* W4 = (const float*)d_in[11];
    const float* b4 = (const float*)d_in[12];
    const float* W5 = (const float*)d_in[13];
    const float* b5 = (const float*)d_in[14];
    const float* g2 = (const float*)d_in[15];
    const float* be2= (const float*)d_in[16];
    const float* W6 = (const float*)d_in[17];
    const float* b6 = (const float*)d_in[18];
    float* out = (float*)d_out;

    float *h_ptr = nullptr, *a_ptr = nullptr;
    cudaGetSymbolAddress((void**)&h_ptr, g_h);
    cudaGetSymbolAddress((void**)&a_ptr, g_a);

    const int TB = 256;
    int gridN    = (Nn + TB - 1) / TB;        // 391
    int gridE    = (Ee + TB - 1) / TB;
    int gridGemm = (Nn + 127) / 128;
    int gridG32  = (Nn + 7) / 8;              // 8 nodes/block (1 warp each)
    int gridG128 = (Nn + 3) / 4;              // 4 nodes/block (2 warps each)

    k_zero_misc<<<gridN, TB>>>();
    k_deg<<<gridE, TB>>>(dst);

    // CSR build (scan1 also computes dinv)
    k_scan1<<<SCAN_BLOCKS, 256>>>();
    k_scan2<<<1, 512>>>();
    k_scan3<<<SCAN_BLOCKS, 256>>>();
    k_fill<<<gridE, TB>>>(src, dst);

    // conv1 (aggregate-first): xa = A'x (32-wide gather) ; g_a = relu(xa@W1 + b1)
    k_gather32<<<gridG32, TB>>>(x);
    k_gemm<LOAD_NONE, true, true, false, false><<<gridGemm, TB>>>(h_ptr, W1, b1, a_ptr, FIN);

    // conv2: g_h = g_a@W2 (already relu'd) ; SELF base in-place ; gather -> g_a
    k_gemm<LOAD_NONE, false, false, true, false><<<gridGemm, TB>>>(a_ptr, W2, b2, h_ptr, Wd);
    k_gather<<<gridG128, TB>>>();

    // mlp_first: g_h = relu(g_a)@W3 + b3 (fused BN stats)
    k_gemm<LOAD_RELU, true, false, false, true><<<gridGemm, TB>>>(a_ptr, W3, b3, h_ptr, Wd);
    k_bnfin<<<1, 128>>>(g1, be1);
    // g_a = relu( relu(bn(g_h)) @ W4 + b4 )
    k_gemm<LOAD_BN, true, true, false, false><<<gridGemm, TB>>>(h_ptr, W4, b4, a_ptr, Wd);

    // global max pool + head
    k_segmax<<<Nn / POOL_ROWS, 128>>>(batch);
    k_final<<<1, 256>>>(W5, b5, g2, be2, W6, b6, out);
}

// round 16
// speedup vs baseline: 1.1051x; 1.1051x over previous
#include <cuda_runtime.h>
#include <cstdint>

// ---------------- problem constants ----------------
#define Nn   100000
#define Ee   600000
#define Gg   64
#define FIN  32
#define Wd   128
#define EPSv 1e-5f

// ---------------- device scratch (static, no allocs) ----------------
__device__ float g_h[(size_t)Nn * Wd];     // conv output; also [N,32] xa for conv1
__device__ float g_a[(size_t)Nn * Wd];     // activations / self-base (in-place gather)
__device__ float g_dinv[Nn];
__device__ int   g_deg[Nn];
__device__ float g_stats[2 * Wd];
__device__ float g_pool[Gg * Wd];
// CSR (edges grouped by dst)
__device__ int   g_rowptr[Nn + 1];
__device__ int   g_cursor[Nn];
__device__ int   g_esrc[Ee];
__device__ int   g_blk[512];

#define SCAN_BLOCKS 391

// ---------------- zero / degree ----------------
__global__ void k_zero_misc() {
    int i = blockIdx.x * blockDim.x + threadIdx.x;
    if (i < Nn) { g_deg[i] = 0; g_cursor[i] = 0; }
    if (i < 2 * Wd) g_stats[i] = 0.f;
    if (i < Gg * Wd) g_pool[i] = 0.f;
}

__global__ void k_deg(const int* __restrict__ dst) {
    int e = blockIdx.x * blockDim.x + threadIdx.x;
    if (e < Ee) atomicAdd(&g_deg[dst[e]], 1);
}

// ---------------- CSR build (scan1 also computes dinv) ----------------
__global__ void k_scan1() {
    __shared__ int sh[256];
    int i = blockIdx.x * 256 + threadIdx.x;
    int d = (i < Nn) ? g_deg[i] : 0;
    if (i < Nn) g_dinv[i] = rsqrtf((float)d + 1.0f);
    sh[threadIdx.x] = d;
    __syncthreads();
    for (int s = 128; s > 0; s >>= 1) {
        if (threadIdx.x < s) sh[threadIdx.x] += sh[threadIdx.x + s];
        __syncthreads();
    }
    if (threadIdx.x == 0) g_blk[blockIdx.x] = sh[0];
}

__global__ void k_scan2() {
    __shared__ int sh[512];
    int t = threadIdx.x;
    sh[t] = (t < SCAN_BLOCKS) ? g_blk[t] : 0;
    __syncthreads();
    int val = sh[t];
    for (int off = 1; off < 512; off <<= 1) {
        int v = (t >= off) ? sh[t - off] : 0;
        __syncthreads();
        sh[t] += v;
        __syncthreads();
    }
    if (t < SCAN_BLOCKS) g_blk[t] = sh[t] - val;
    if (t == 0) g_rowptr[Nn] = Ee;
}

__global__ void k_scan3() {
    __shared__ int sh[256];
    int i = blockIdx.x * 256 + threadIdx.x;
    int t = threadIdx.x;
    int val = (i < Nn) ? g_deg[i] : 0;
    sh[t] = val;
    __syncthreads();
    for (int off = 1; off < 256; off <<= 1) {
        int v = (t >= off) ? sh[t - off] : 0;
        __syncthreads();
        sh[t] += v;
        __syncthreads();
    }
    if (i < Nn) g_rowptr[i] = g_blk[blockIdx.x] + sh[t] - val;
}

__global__ void k_fill(const int* __restrict__ src, const int* __restrict__ dst) {
    int e = blockIdx.x * blockDim.x + threadIdx.x;
    if (e >= Ee) return;
    int d = dst[e];
    int pos = g_rowptr[d] + atomicAdd(&g_cursor[d], 1);
    g_esrc[pos] = src[e];
}

// ---------------- gather32: xa[n] = dinv^2*x[n] + sum_e dinv_s*dinv_n*x[s] ----------------
// one warp per node, 1 feature (of 32) per lane; writes g_h used as [N,32].
__global__ void k_gather32(const float* __restrict__ x) {
    int n = blockIdx.x * 8 + (threadIdx.x >> 5);
    if (n >= Nn) return;
    int lane = threadIdx.x & 31;
    int beg = g_rowptr[n], end = g_rowptr[n + 1];
    float dn = g_dinv[n];
    float acc = x[(size_t)n * FIN + lane] * dn * dn;
    int e = beg;
    for (; e + 4 <= end; e += 4) {
        int s0 = g_esrc[e], s1 = g_esrc[e + 1], s2 = g_esrc[e + 2], s3 = g_esrc[e + 3];
        float w0 = g_dinv[s0] * dn, w1 = g_dinv[s1] * dn;
        float w2 = g_dinv[s2] * dn, w3 = g_dinv[s3] * dn;
        float v0 = x[(size_t)s0 * FIN + lane];
        float v1 = x[(size_t)s1 * FIN + lane];
        float v2 = x[(size_t)s2 * FIN + lane];
        float v3 = x[(size_t)s3 * FIN + lane];
        acc = fmaf(v0, w0, acc);
        acc = fmaf(v1, w1, acc);
        acc = fmaf(v2, w2, acc);
        acc = fmaf(v3, w3, acc);
    }
    for (; e < end; e++) {
        int s = g_esrc[e];
        acc = fmaf(x[(size_t)s * FIN + lane], g_dinv[s] * dn, acc);
    }
    g_h[(size_t)n * FIN + lane] = acc;
}

// ---------------- CSR gather 128-wide (in-place on g_a, 4x unrolled) ----------------
__global__ void k_gather() {
    int n = blockIdx.x * 8 + (threadIdx.x >> 5);
    if (n >= Nn) return;
    int lane = threadIdx.x & 31;
    int beg = g_rowptr[n], end = g_rowptr[n + 1];
    float dn = g_dinv[n];
    float4 acc = *(const float4*)&g_a[(size_t)n * Wd + lane * 4];
    int e = beg;
    for (; e + 4 <= end; e += 4) {
        int s0 = g_esrc[e], s1 = g_esrc[e + 1], s2 = g_esrc[e + 2], s3 = g_esrc[e + 3];
        float w0 = g_dinv[s0] * dn, w1 = g_dinv[s1] * dn;
        float w2 = g_dinv[s2] * dn, w3 = g_dinv[s3] * dn;
        float4 v0 = *(const float4*)&g_h[(size_t)s0 * Wd + lane * 4];
        float4 v1 = *(const float4*)&g_h[(size_t)s1 * Wd + lane * 4];
        float4 v2 = *(const float4*)&g_h[(size_t)s2 * Wd + lane * 4];
        float4 v3 = *(const float4*)&g_h[(size_t)s3 * Wd + lane * 4];
        acc.x = fmaf(v0.x, w0, acc.x); acc.y = fmaf(v0.y, w0, acc.y);
        acc.z = fmaf(v0.z, w0, acc.z); acc.w = fmaf(v0.w, w0, acc.w);
        acc.x = fmaf(v1.x, w1, acc.x); acc.y = fmaf(v1.y, w1, acc.y);
        acc.z = fmaf(v1.z, w1, acc.z); acc.w = fmaf(v1.w, w1, acc.w);
        acc.x = fmaf(v2.x, w2, acc.x); acc.y = fmaf(v2.y, w2, acc.y);
        acc.z = fmaf(v2.z, w2, acc.z); acc.w = fmaf(v2.w, w2, acc.w);
        acc.x = fmaf(v3.x, w3, acc.x); acc.y = fmaf(v3.y, w3, acc.y);
        acc.z = fmaf(v3.z, w3, acc.z); acc.w = fmaf(v3.w, w3, acc.w);
    }
    for (; e < end; e++) {
        int s = g_esrc[e];
        float w = g_dinv[s] * dn;
        float4 v = *(const float4*)&g_h[(size_t)s * Wd + lane * 4];
        acc.x = fmaf(v.x, w, acc.x); acc.y = fmaf(v.y, w, acc.y);
        acc.z = fmaf(v.z, w, acc.z); acc.w = fmaf(v.w, w, acc.w);
    }
    *(float4*)&g_a[(size_t)n * Wd + lane * 4] = acc;
}

// ---------------- fused fp32 SGEMM v2 (proven best) ----------------
// 128x128 tile, 256 threads, 8x8 microtile, packed fma.rn.f32x2,
// double-buffered smem, reg prefetch, 2 CTAs/SM.
enum { LOAD_NONE = 0, LOAD_RELU = 1, LOAD_BN = 2 };

template <int LOADM, bool BIAS, bool RELU, bool SELF, bool STATS>
__global__ __launch_bounds__(256, 2) void k_gemm(const float* __restrict__ A,
                                                 const float* __restrict__ Bm,
                                                 const float* __restrict__ bias,
                                                 float* __restrict__ C, int K) {
    __shared__ float As[2][16][132];
    __shared__ float Bs[2][16][128];
    __shared__ float s_st[2][128];

    int tid = threadIdx.x;
    int rb  = blockIdx.x * 128;
    int tx  = tid & 15;
    int ty  = tid >> 4;
    int lr  = tid >> 2;
    int kq  = (tid & 3) * 4;
    int bk  = tid >> 4;
    int bc  = (tid & 15) * 8;

    float4 pa[2], pb[2];

    auto ldTile = [&](int kc) {
#pragma unroll
        for (int h = 0; h < 2; h++) {
            int r = rb + lr + h * 64;
            float4 v = make_float4(0.f, 0.f, 0.f, 0.f);
            if (r < Nn) v = *(const float4*)&A[(size_t)r * K + kc * 16 + kq];
            pa[h] = v;
        }
        const float* bp = &Bm[(size_t)(kc * 16 + bk) * Wd + bc];
        pb[0] = *(const float4*)bp;
        pb[1] = *(const float4*)(bp + 4);
    };

    auto stTile = [&](int buf, int kc) {
#pragma unroll
        for (int h = 0; h < 2; h++) {
            float4 v = pa[h];
            if (LOADM == LOAD_RELU) {
                v.x = fmaxf(v.x, 0.f); v.y = fmaxf(v.y, 0.f);
                v.z = fmaxf(v.z, 0.f); v.w = fmaxf(v.w, 0.f);
            } else if (LOADM == LOAD_BN) {
                int c0 = kc * 16 + kq;
                v.x = fmaxf(fmaf(v.x, g_stats[c0 + 0], g_stats[Wd + c0 + 0]), 0.f);
                v.y = fmaxf(fmaf(v.y, g_stats[c0 + 1], g_stats[Wd + c0 + 1]), 0.f);
                v.z = fmaxf(fmaf(v.z, g_stats[c0 + 2], g_stats[Wd + c0 + 2]), 0.f);
                v.w = fmaxf(fmaf(v.w, g_stats[c0 + 3], g_stats[Wd + c0 + 3]), 0.f);
            }
            As[buf][kq + 0][lr + h * 64] = v.x;
            As[buf][kq + 1][lr + h * 64] = v.y;
            As[buf][kq + 2][lr + h * 64] = v.z;
            As[buf][kq + 3][lr + h * 64] = v.w;
        }
        *(float4*)&Bs[buf][bk][bc]     = pb[0];
        *(float4*)&Bs[buf][bk][bc + 4] = pb[1];
    };

    unsigned long long acc[8][4];
#pragma unroll
    for (int i = 0; i < 8; i++)
#pragma unroll
        for (int j = 0; j < 4; j++) acc[i][j] = 0ull;

    int nk = K >> 4;
    ldTile(0);
    stTile(0, 0);
    __syncthreads();

    for (int kc = 0; kc < nk; kc++) {
        if (kc + 1 < nk) ldTile(kc + 1);
        int buf = kc & 1;
#pragma unroll
        for (int k = 0; k < 16; k++) {
            float4 a0 = *(const float4*)&As[buf][k][ty * 8];
            float4 a1 = *(const float4*)&As[buf][k][ty * 8 + 4];
            ulonglong2 b0 = *(const ulonglong2*)&Bs[buf][k][tx * 8];
            ulonglong2 b1 = *(const ulonglong2*)&Bs[buf][k][tx * 8 + 4];
            unsigned long long bb[4] = {b0.x, b0.y, b1.x, b1.y};
            float av[8] = {a0.x, a0.y, a0.z, a0.w, a1.x, a1.y, a1.z, a1.w};
#pragma unroll
            for (int i = 0; i < 8; i++) {
                unsigned long long ad;
                unsigned int ai = __float_as_uint(av[i]);
                asm("mov.b64 %0, {%1, %1};" : "=l"(ad) : "r"(ai));
#pragma unroll
                for (int j = 0; j < 4; j++)
                    asm("fma.rn.f32x2 %0, %1, %2, %0;"
                        : "+l"(acc[i][j]) : "l"(ad), "l"(bb[j]));
            }
        }
        if (kc + 1 < nk) {
            stTile((kc + 1) & 1, kc + 1);
            __syncthreads();
        }
    }

    // ---------------- epilogue ----------------
    if (STATS) {
        s_st[tid >> 7][tid & 127] = 0.f;
        __syncthreads();
    }

    float cs[8], cq[8];
    if (STATS) {
#pragma unroll
        for (int j = 0; j < 8; j++) { cs[j] = 0.f; cq[j] = 0.f; }
    }

#pragma unroll
    for (int i = 0; i < 8; i++) {
        int r = rb + ty * 8 + i;
        if (r < Nn) {
            float out[8];
#pragma unroll
            for (int j = 0; j < 4; j++) {
                union { unsigned long long u; float2 f; } t;
                t.u = acc[i][j];
                out[2 * j]     = t.f.x;
                out[2 * j + 1] = t.f.y;
            }
            float os[8];
#pragma unroll
            for (int j = 0; j < 8; j++) {
                float v = out[j];
                if (BIAS) v += bias[tx * 8 + j];
                if (RELU) v = fmaxf(v, 0.f);
                os[j] = v;
                if (STATS) { cs[j] += v; cq[j] += v * v; }
            }
            float* cp = &C[(size_t)r * Wd + tx * 8];
            *(float4*)(cp)     = make_float4(os[0], os[1], os[2], os[3]);
            *(float4*)(cp + 4) = make_float4(os[4], os[5], os[6], os[7]);
            if (SELF) {
                float dv = g_dinv[r];
                float ds = dv * dv;
                float* ap = &g_a[(size_t)r * Wd + tx * 8];
                float4 s0, s1;
                s0.x = fmaf(out[0], ds, bias[tx * 8 + 0]);
                s0.y = fmaf(out[1], ds, bias[tx * 8 + 1]);
                s0.z = fmaf(out[2], ds, bias[tx * 8 + 2]);
                s0.w = fmaf(out[3], ds, bias[tx * 8 + 3]);
                s1.x = fmaf(out[4], ds, bias[tx * 8 + 4]);
                s1.y = fmaf(out[5], ds, bias[tx * 8 + 5]);
                s1.z = fmaf(out[6], ds, bias[tx * 8 + 6]);
                s1.w = fmaf(out[7], ds, bias[tx * 8 + 7]);
                *(float4*)(ap)     = s0;
                *(float4*)(ap + 4) = s1;
            }
        }
    }

    if (STATS) {
#pragma unroll
        for (int j = 0; j < 8; j++) {
            atomicAdd(&s_st[0][tx * 8 + j], cs[j]);
            atomicAdd(&s_st[1][tx * 8 + j], cq[j]);
        }
        __syncthreads();
        if (tid < 128) {
            atomicAdd(&g_stats[tid],      s_st[0][tid]);
            atomicAdd(&g_stats[Wd + tid], s_st[1][tid]);
        }
    }
}

// ---------------- BN finalize ----------------
__global__ void k_bnfin(const float* __restrict__ gamma, const float* __restrict__ beta) {
    int c = threadIdx.x;  // 128
    float mu  = g_stats[c] * (1.f / Nn);
    float var = g_stats[Wd + c] * (1.f / Nn) - mu * mu;
    float rs  = rsqrtf(var + EPSv);
    float sc  = gamma[c] * rs;
    g_stats[c]      = sc;
    g_stats[Wd + c] = beta[c] - mu * sc;
}

// ---------------- per-graph max pool (batch is sorted) ----------------
#define POOL_ROWS 250
__global__ void k_segmax(const int* __restrict__ batch) {
    int c  = threadIdx.x;
    int r0 = blockIdx.x * POOL_ROWS;
    int r1 = r0 + POOL_ROWS;
    int cur = batch[r0];
    float m = g_a[(size_t)r0 * Wd + c];
#pragma unroll 4
    for (int r = r0 + 1; r < r1; r++) {
        int gID = batch[r];
        float v = g_a[(size_t)r * Wd + c];
        if (gID != cur) {
            atomicMax((int*)&g_pool[cur * Wd + c], __float_as_int(m));
            cur = gID;
            m = v;
        } else {
            m = fmaxf(m, v);
        }
    }
    atomicMax((int*)&g_pool[cur * Wd + c], __float_as_int(m));
}

// ---------------- head MLP ----------------
__global__ void k_final(const float* __restrict__ W5, const float* __restrict__ b5,
                        const float* __restrict__ g2, const float* __restrict__ be2,
                        const float* __restrict__ W6, const float* __restrict__ b6,
                        float* __restrict__ out) {
    __shared__ float S[64][65];
    __shared__ float sc[64], tc[64];
    int tid = threadIdx.x;
    for (int idx = tid; idx < 64 * 64; idx += 256) {
        int r = idx >> 6, c = idx & 63;
        float acc = b5[c];
        for (int k = 0; k < 128; k++) acc = fmaf(g_pool[r * 128 + k], W5[k * 64 + c], acc);
        S[r][c] = acc;
    }
    __syncthreads();
    if (tid < 64) {
        int c = tid;
        float s = 0.f, q = 0.f;
        for (int r = 0; r < 64; r++) { float v = S[r][c]; s += v; q += v * v; }
        float mu  = s * (1.f / 64);
        float var = q * (1.f / 64) - mu * mu;
        float rs  = rsqrtf(var + EPSv);
        float s_  = g2[c] * rs;
        sc[c] = s_;
        tc[c] = be2[c] - mu * s_;
    }
    __syncthreads();
    if (tid < 64) {
        int r = tid;
        float o = b6[0];
        for (int c = 0; c < 64; c++) {
            float v = fmaxf(fmaf(S[r][c], sc[c], tc[c]), 0.f);
            o = fmaf(v, W6[c], o);
        }
        out[r] = o;
    }
}

// ---------------- launch ----------------
extern "C" void kernel_launch(void* const* d_in, const int* in_sizes, int n_in,
                              void* d_out, int out_size) {
    const float* x    = (const float*)d_in[0];
    const int*   ei   = (const int*)d_in[1];
    const int*   src  = ei;
    const int*   dst  = ei + Ee;
    const int*   batch= (const int*)d_in[2];
    const float* W1 = (const float*)d_in[3];
    const float* b1 = (const float*)d_in[4];
    const float* W2 = (const float*)d_in[5];
    const float* b2 = (const float*)d_in[6];
    const float* W3 = (const float*)d_in[7];
    const float* b3 = (const float*)d_in[8];
    const float* g1 = (const float*)d_in[9];
    const float* be1= (const float*)d_in[10];
    const float* W4 = (const float*)d_in[11];
    const float* b4 = (const float*)d_in[12];
    const float* W5 = (const float*)d_in[13];
    const float* b5 = (const float*)d_in[14];
    const float* g2 = (const float*)d_in[15];
    const float* be2= (const float*)d_in[16];
    const float* W6 = (const float*)d_in[17];
    const float* b6 = (const float*)d_in[18];
    float* out = (float*)d_out;

    float *h_ptr = nullptr, *a_ptr = nullptr;
    cudaGetSymbolAddress((void**)&h_ptr, g_h);
    cudaGetSymbolAddress((void**)&a_ptr, g_a);

    const int TB = 256;
    int gridN    = (Nn + TB - 1) / TB;        // 391
    int gridE    = (Ee + TB - 1) / TB;
    int gridGemm = (Nn + 127) / 128;
    int gridGath = (Nn + 7) / 8;

    k_zero_misc<<<gridN, TB>>>();
    k_deg<<<gridE, TB>>>(dst);

    // CSR build (scan1 also computes dinv)
    k_scan1<<<SCAN_BLOCKS, 256>>>();
    k_scan2<<<1, 512>>>();
    k_scan3<<<SCAN_BLOCKS, 256>>>();
    k_fill<<<gridE, TB>>>(src, dst);

    // conv1 (aggregate-first): xa = A'x (32-wide gather) ; g_a = relu(xa@W1 + b1)
    k_gather32<<<gridGath, TB>>>(x);
    k_gemm<LOAD_NONE, true, true, false, false><<<gridGemm, TB>>>(h_ptr, W1, b1, a_ptr, FIN);

    // conv2: g_h = g_a@W2 (already relu'd) ; SELF base in-place ; gather -> g_a
    k_gemm<LOAD_NONE, false, false, true, false><<<gridGemm, TB>>>(a_ptr, W2, b2, h_ptr, Wd);
    k_gather<<<gridGath, TB>>>();

    // mlp_first: g_h = relu(g_a)@W3 + b3 (fused BN stats)
    k_gemm<LOAD_RELU, true, false, false, true><<<gridGemm, TB>>>(a_ptr, W3, b3, h_ptr, Wd);
    k_bnfin<<<1, 128>>>(g1, be1);
    // g_a = relu( relu(bn(g_h)) @ W4 + b4 )
    k_gemm<LOAD_BN, true, true, false, false><<<gridGemm, TB>>>(h_ptr, W4, b4, a_ptr, Wd);

    // global max pool + head
    k_segmax<<<Nn / POOL_ROWS, 128>>>(batch);
    k_final<<<1, 256>>>(W5, b5, g2, be2, W6, b6, out);
}